// round 15
// baseline (speedup 1.0000x reference)
#include <cuda_runtime.h>
#include <cuda_bf16.h>
#include <cuda_fp16.h>

// ---------------------------------------------------------------------------
// 2-layer GCN. Bucketed CSR (CAP=96), (src,w) packed uint2.
// Fork: gemm1 on s2, bucket_fill on s3, degree chain on main.
// Layer 2 = FUSED kernel: A-tile staging IS the layer-1 aggregate
// (gather h16 + bias1 + relu -> fp16 smem tile) followed by MMA with W2.
// Fused output goes to a separate buffer (hb) to avoid WAR vs the h16 gather.
// ---------------------------------------------------------------------------

#define C 128
#define NMAX 50048
#define CAP 96

__device__ float  g_dinv[NMAX];
__device__ int    g_cursor[NMAX];
__device__ uint2  g_pairs[(size_t)NMAX * CAP];   // (src, f32 bits of weight)
__device__ __half g_h16[(size_t)NMAX * C];   // layer-1 GEMM result
__device__ __half g_hb[(size_t)NMAX * C];    // fused (agg1+gemm2) output

// ---------------- init ------------------------------------------------------
__global__ void init_zero(float* deg, int* cursor, int n) {
    int i = blockIdx.x * blockDim.x + threadIdx.x;
    if (i < n) { deg[i] = 0.0f; cursor[i] = 0; }
}

__global__ void deg_scatter(const int* __restrict__ dst,
                            const float* __restrict__ w,
                            float* deg, int E) {
    int e = blockIdx.x * blockDim.x + threadIdx.x;
    if (e < E) atomicAdd(&deg[dst[e]], w[e]);
}

__global__ void deg_fin(float* deg, int n) {
    int i = blockIdx.x * blockDim.x + threadIdx.x;
    if (i < n) deg[i] = rsqrtf(1.0f + deg[i]);   // self-loop weight folded in
}

// ---------------- bucket fill (independent of degree pass) ------------------
__global__ void bucket_fill(const int* __restrict__ src,
                            const int* __restrict__ dst,
                            const float* __restrict__ w,
                            int* cursor, uint2* __restrict__ pairs, int E) {
    int e = blockIdx.x * blockDim.x + threadIdx.x;
    if (e >= E) return;
    int d = dst[e];
    int pos = atomicAdd(&cursor[d], 1);
    if (pos < CAP) {
        uint2 p;
        p.x = (unsigned)src[e];
        p.y = __float_as_uint(w[e]);
        pairs[(size_t)d * CAP + pos] = p;
    }
}

// ---------------- shared gather-aggregate core -------------------------------
__device__ __forceinline__ float4 h4_load(const __half* h, int node, int lane) {
    uint2 raw = ((const uint2*)(h + (size_t)node * C))[lane];
    float2 p0 = __half22float2(*(__half2*)&raw.x);
    float2 p1 = __half22float2(*(__half2*)&raw.y);
    return make_float4(p0.x, p0.y, p1.x, p1.y);
}

// acc for one node: relu( dinv*(dinv*h[node] + sum v*dinv[s]*h[s]) + bias )
__device__ __forceinline__ float4 node_agg(const __half* __restrict__ h,
                                           const int* __restrict__ cursor,
                                           const uint2* __restrict__ pairs,
                                           const float* __restrict__ dinv,
                                           const float* __restrict__ bias,
                                           int node, int lane) {
    float di = dinv[node];
    float4 acc = h4_load(h, node, lane);
    acc.x *= di; acc.y *= di; acc.z *= di; acc.w *= di;

    const size_t base = (size_t)node * CAP;
    int cnt = cursor[node];
    cnt = cnt < CAP ? cnt : CAP;

    int j = 0;
    for (; j + 7 < cnt; j += 8) {
        uint2 p[8];
        #pragma unroll
        for (int k = 0; k < 8; k++) p[k] = pairs[base + j + k];
        #pragma unroll
        for (int k = 0; k < 8; k++) {
            int s = (int)p[k].x;
            float v = __uint_as_float(p[k].y) * dinv[s];
            float4 hh = h4_load(h, s, lane);
            acc.x += v * hh.x; acc.y += v * hh.y;
            acc.z += v * hh.z; acc.w += v * hh.w;
        }
    }
    for (; j + 3 < cnt; j += 4) {
        uint2 p[4];
        #pragma unroll
        for (int k = 0; k < 4; k++) p[k] = pairs[base + j + k];
        #pragma unroll
        for (int k = 0; k < 4; k++) {
            int s = (int)p[k].x;
            float v = __uint_as_float(p[k].y) * dinv[s];
            float4 hh = h4_load(h, s, lane);
            acc.x += v * hh.x; acc.y += v * hh.y;
            acc.z += v * hh.z; acc.w += v * hh.w;
        }
    }
    for (; j < cnt; j++) {
        uint2 p = pairs[base + j];
        int s = (int)p.x;
        float v = __uint_as_float(p.y) * dinv[s];
        float4 hh = h4_load(h, s, lane);
        acc.x += v * hh.x; acc.y += v * hh.y;
        acc.z += v * hh.z; acc.w += v * hh.w;
    }

    float4 bv = *(const float4*)&bias[lane * 4];
    acc.x = fmaxf(acc.x * di + bv.x, 0.f);
    acc.y = fmaxf(acc.y * di + bv.y, 0.f);
    acc.z = fmaxf(acc.z * di + bv.z, 0.f);
    acc.w = fmaxf(acc.w * di + bv.w, 0.f);
    return acc;
}

// ---------------- GEMM common ------------------------------------------------
#define MMAF16(d, a0, a1, a2, a3, b0, b1)                                     \
    asm volatile("mma.sync.aligned.m16n8k16.row.col.f32.f16.f16.f32 "         \
                 "{%0,%1,%2,%3}, {%4,%5,%6,%7}, {%8,%9}, {%0,%1,%2,%3};"      \
                 : "+f"(d[0]), "+f"(d[1]), "+f"(d[2]), "+f"(d[3])             \
                 : "r"(a0), "r"(a1), "r"(a2), "r"(a3), "r"(b0), "r"(b1))

__device__ __forceinline__ uint4 ldsm4(unsigned addr) {
    uint4 r;
    asm volatile("ldmatrix.sync.aligned.m8n8.x4.shared.b16 {%0,%1,%2,%3}, [%4];"
                 : "=r"(r.x), "=r"(r.y), "=r"(r.z), "=r"(r.w) : "r"(addr));
    return r;
}

#define PXW_OFF (64 * 68)
#define PLAIN_SMEM_WORDS (64 * 68 + 128 * 68)   // 52224 B

// stage W^T fp16 into whf (once per block)
__device__ __forceinline__ void stage_w(const float* __restrict__ W,
                                        unsigned* whf, int t) {
    for (int i = t; i < 64 * 128; i += 256) {
        int k2 = i >> 7, nn = i & 127;
        float a = W[(size_t)(2 * k2) * 128 + nn];
        float b = W[(size_t)(2 * k2 + 1) * 128 + nn];
        __half2 h2 = __floats2half2_rn(a, b);
        whf[nn * 68 + k2] = *(unsigned*)&h2;
    }
}

// MMA + epilogue over the staged tile (shared by both GEMM kernels)
__device__ __forceinline__ void mma_and_store(
        unsigned aAddr, const unsigned* bAddr, __half* __restrict__ O,
        int tile, int n, int mb, int nb, int gid, int tig) {
    float acc[8][4];
    #pragma unroll
    for (int i = 0; i < 8; i++)
        #pragma unroll
        for (int j = 0; j < 4; j++) acc[i][j] = 0.f;

    #pragma unroll
    for (int kk = 0; kk < 8; kk++) {
        const unsigned off = kk * 32;
        uint4 a = ldsm4(aAddr + off);
        #pragma unroll
        for (int p = 0; p < 4; p++) {
            uint4 b = ldsm4(bAddr[p] + off);
            MMAF16(acc[2 * p],     a.x, a.y, a.z, a.w, b.x, b.y);
            MMAF16(acc[2 * p + 1], a.x, a.y, a.z, a.w, b.z, b.w);
        }
    }

    const int r0 = tile * 64 + mb + gid;
    #pragma unroll
    for (int nt = 0; nt < 8; nt++) {
        int c = nb + nt * 8 + 2 * tig;
        if (r0 < n)
            *(__half2*)&O[(size_t)r0 * 128 + c] =
                __floats2half2_rn(acc[nt][0], acc[nt][1]);
        if (r0 + 8 < n)
            *(__half2*)&O[(size_t)(r0 + 8) * 128 + c] =
                __floats2half2_rn(acc[nt][2], acc[nt][3]);
    }
}

// ---------------- gemm1: O = X(fp32) @ W, prefetch-pipelined ----------------
__global__ void __launch_bounds__(256, 2)
gemm_f32(const float* __restrict__ X, const float* __restrict__ W,
         __half* __restrict__ O, int n, int ntiles) {
    extern __shared__ unsigned smu[];
    unsigned* xhf = smu;
    unsigned* whf = smu + PXW_OFF;

    const int t = threadIdx.x;
    stage_w(W, whf, t);

    const int lane = t & 31, w = t >> 5;
    const int mb = (w & 3) * 16, nb = (w >> 2) * 64;
    const int gid = lane >> 2, tig = lane & 3;

    const unsigned sbase = (unsigned)__cvta_generic_to_shared(smu);
    const int mat = lane >> 3, r8 = lane & 7;
    unsigned aAddr = sbase + (unsigned)(((mb + (mat & 1) * 8 + r8) * 68
                                         + (mat >> 1) * 4) * 4);
    unsigned bAddr[4];
    #pragma unroll
    for (int p = 0; p < 4; p++)
        bAddr[p] = sbase + (unsigned)((PXW_OFF
                       + (nb + p * 16 + (mat >> 1) * 8 + r8) * 68
                       + (mat & 1) * 4) * 4);

    float4 pf[8];
    int tile = blockIdx.x;
    if (tile < ntiles) {
        const float4* Xv = (const float4*)(X + (size_t)tile * 64 * 128);
        #pragma unroll
        for (int i = 0; i < 8; i++) {
            int idx = t + i * 256, r = idx >> 5;
            pf[i] = make_float4(0.f, 0.f, 0.f, 0.f);
            if (tile * 64 + r < n) pf[i] = Xv[idx];
        }
    }

    while (tile < ntiles) {
        __syncthreads();
        #pragma unroll
        for (int i = 0; i < 8; i++) {
            int idx = t + i * 256;
            int r = idx >> 5, c4 = idx & 31;
            float4 v = pf[i];
            __half2 h0 = __floats2half2_rn(v.x, v.y);
            __half2 h1 = __floats2half2_rn(v.z, v.w);
            xhf[r * 68 + 2 * c4]     = *(unsigned*)&h0;
            xhf[r * 68 + 2 * c4 + 1] = *(unsigned*)&h1;
        }
        __syncthreads();

        const int next = tile + gridDim.x;
        if (next < ntiles) {
            const float4* Xv = (const float4*)(X + (size_t)next * 64 * 128);
            #pragma unroll
            for (int i = 0; i < 8; i++) {
                int idx = t + i * 256, r = idx >> 5;
                pf[i] = make_float4(0.f, 0.f, 0.f, 0.f);
                if (next * 64 + r < n) pf[i] = Xv[idx];
            }
        }

        mma_and_store(aAddr, bAddr, O, tile, n, mb, nb, gid, tig);
        tile = next;
    }
}

// ---------------- FUSED: agg1(h16)+bias1+relu -> A tile -> @ W2 -> hb -------
__global__ void __launch_bounds__(256, 2)
gemm_fused(const __half* __restrict__ H, const float* __restrict__ W,
           const int* __restrict__ cursor, const uint2* __restrict__ pairs,
           const float* __restrict__ dinv, const float* __restrict__ bias,
           __half* __restrict__ O, int n, int ntiles) {
    extern __shared__ unsigned smu[];
    unsigned* xhf = smu;
    unsigned* whf = smu + PXW_OFF;

    const int t = threadIdx.x;
    stage_w(W, whf, t);

    const int lane = t & 31, w = t >> 5;
    const int mb = (w & 3) * 16, nb = (w >> 2) * 64;
    const int gid = lane >> 2, tig = lane & 3;

    const unsigned sbase = (unsigned)__cvta_generic_to_shared(smu);
    const int mat = lane >> 3, r8 = lane & 7;
    unsigned aAddr = sbase + (unsigned)(((mb + (mat & 1) * 8 + r8) * 68
                                         + (mat >> 1) * 4) * 4);
    unsigned bAddr[4];
    #pragma unroll
    for (int p = 0; p < 4; p++)
        bAddr[p] = sbase + (unsigned)((PXW_OFF
                       + (nb + p * 16 + (mat >> 1) * 8 + r8) * 68
                       + (mat & 1) * 4) * 4);

    for (int tile = blockIdx.x; tile < ntiles; tile += gridDim.x) {
        __syncthreads();   // prev iter's ldsm reads done; W ready on 1st iter
        // --- A-tile staging IS the layer-1 aggregate: warp w -> rows w*8.. --
        #pragma unroll 1
        for (int r = 0; r < 8; r++) {
            int row = w * 8 + r;
            int node = tile * 64 + row;
            unsigned w0 = 0, w1 = 0;
            if (node < n) {
                float4 acc = node_agg(H, cursor, pairs, dinv, bias,
                                      node, lane);
                __half2 p0 = __floats2half2_rn(acc.x, acc.y);
                __half2 p1 = __floats2half2_rn(acc.z, acc.w);
                w0 = *(unsigned*)&p0; w1 = *(unsigned*)&p1;
            }
            xhf[row * 68 + 2 * lane]     = w0;
            xhf[row * 68 + 2 * lane + 1] = w1;
        }
        __syncthreads();

        mma_and_store(aAddr, bAddr, O, tile, n, mb, nb, gid, tig);
    }
}

// ---------------- final aggregate (fp32 out) --------------------------------
__global__ void aggregate_out(const __half* __restrict__ h,
                              const int* __restrict__ cursor,
                              const uint2* __restrict__ pairs,
                              const float* __restrict__ dinv,
                              const float* __restrict__ bias,
                              float* __restrict__ out, int n) {
    int node = blockIdx.x * (blockDim.x >> 5) + (threadIdx.x >> 5);
    int lane = threadIdx.x & 31;
    if (node >= n) return;
    float4 acc = node_agg(h, cursor, pairs, dinv, bias, node, lane);
    ((float4*)(out + (size_t)node * C))[lane] = acc;
}

// ---------------------------------------------------------------------------
extern "C" void kernel_launch(void* const* d_in, const int* in_sizes, int n_in,
                              void* d_out, int out_size) {
    const float* x  = (const float*)d_in[0];
    const int*   ei = (const int*)d_in[1];     // [2, E] int32
    const float* ew = (const float*)d_in[2];
    const float* W1 = (const float*)d_in[3];
    const float* b1 = (const float*)d_in[4];
    const float* W2 = (const float*)d_in[5];
    const float* b2 = (const float*)d_in[6];
    float* out = (float*)d_out;

    const int N = in_sizes[0] / C;
    const int E = in_sizes[2];
    const int* src = ei;
    const int* dst = ei + E;

    float*  dinv;   cudaGetSymbolAddress((void**)&dinv, g_dinv);
    int*    cursor; cudaGetSymbolAddress((void**)&cursor, g_cursor);
    uint2*  pairs;  cudaGetSymbolAddress((void**)&pairs, g_pairs);
    __half* h16;    cudaGetSymbolAddress((void**)&h16, g_h16);
    __half* hb;     cudaGetSymbolAddress((void**)&hb, g_hb);

    const int PLAIN_SMEM = PLAIN_SMEM_WORDS * (int)sizeof(unsigned);
    cudaFuncSetAttribute(gemm_f32,
                         cudaFuncAttributeMaxDynamicSharedMemorySize, PLAIN_SMEM);
    cudaFuncSetAttribute(gemm_fused,
                         cudaFuncAttributeMaxDynamicSharedMemorySize, PLAIN_SMEM);

    static cudaStream_t s2 = nullptr, s3 = nullptr;
    static cudaEvent_t evFork = nullptr, evM = nullptr, ev2 = nullptr,
                       ev3 = nullptr;
    if (!s2) {
        cudaStreamCreateWithFlags(&s2, cudaStreamNonBlocking);
        cudaStreamCreateWithFlags(&s3, cudaStreamNonBlocking);
        cudaEventCreateWithFlags(&evFork, cudaEventDisableTiming);
        cudaEventCreateWithFlags(&evM, cudaEventDisableTiming);
        cudaEventCreateWithFlags(&ev2, cudaEventDisableTiming);
        cudaEventCreateWithFlags(&ev3, cudaEventDisableTiming);
    }

    dim3 blk(256);
    int gN     = (N + 255) / 256;
    int gE     = (E + 255) / 256;
    int ntiles = (N + 63) / 64;
    int gF     = 296 < ntiles ? 296 : ntiles;   // 2 CTA/SM persistent
    int gAgg   = (N + 7) / 8;

    // ---- fork A: layer-1 GEMM on s2 (independent of graph structure) -------
    cudaEventRecord(evFork, 0);
    cudaStreamWaitEvent(s2, evFork, 0);
    gemm_f32<<<gF, blk, PLAIN_SMEM, s2>>>(x, W1, h16, N, ntiles);
    cudaEventRecord(ev2, s2);

    // ---- main: init, then fork B: bucket fill on s3 concurrent with degree -
    init_zero<<<gN, blk>>>(dinv, cursor, N);
    cudaEventRecord(evM, 0);
    cudaStreamWaitEvent(s3, evM, 0);
    bucket_fill<<<gE, blk, 0, s3>>>(src, dst, ew, cursor, pairs, E);
    cudaEventRecord(ev3, s3);

    deg_scatter<<<gE, blk>>>(dst, ew, dinv, E);
    deg_fin<<<gN, blk>>>(dinv, N);

    cudaStreamWaitEvent(0, ev3, 0);
    cudaStreamWaitEvent(0, ev2, 0);

    // ---- fused agg1 + gemm2 -> hb ----
    gemm_fused<<<gF, blk, PLAIN_SMEM>>>(h16, W2, cursor, pairs, dinv, b1,
                                        hb, N, ntiles);

    // ---- final aggregate (fp32 out) ----
    aggregate_out<<<gAgg, blk>>>(hb, cursor, pairs, dinv, b2, out, N);
}

// round 16
// speedup vs baseline: 1.2271x; 1.2271x over previous
#include <cuda_runtime.h>
#include <cuda_bf16.h>
#include <cuda_fp16.h>

// ---------------------------------------------------------------------------
// 2-layer GCN. Bucketed CSR (CAP=96 >> Poisson(12) max degree), (src,w) packed
// uint2. Fork: gemm1 on s2; CSR build (init -> merged edge pass -> rsqrt) on
// main. Serial tail: agg1 -> gemm2 -> agg2.
// Post-mortem constraints baked in: aggregate stays a standalone kernel
// (R15 fusion and R12/13 stream-overlap both regressed — gather needs
// independent warps for MLP; overlap splits L2 bandwidth).
// ---------------------------------------------------------------------------

#define C 128
#define NMAX 50048
#define CAP 96

__device__ float  g_dinv[NMAX];
__device__ int    g_cursor[NMAX];
__device__ uint2  g_pairs[(size_t)NMAX * CAP];   // (src, f32 bits of weight)
__device__ __half g_h16[(size_t)NMAX * C];   // GEMM result (fp16)
__device__ __half g_a16[(size_t)NMAX * C];   // layer-1 activation (fp16)

// ---------------- init ------------------------------------------------------
__global__ void init_zero(float* deg, int* cursor, int n) {
    int i = blockIdx.x * blockDim.x + threadIdx.x;
    if (i < n) { deg[i] = 0.0f; cursor[i] = 0; }
}

// ---------------- merged edge pass: degree atomic + bucket fill -------------
__global__ void edge_build(const int* __restrict__ src,
                           const int* __restrict__ dst,
                           const float* __restrict__ w,
                           float* deg, int* cursor,
                           uint2* __restrict__ pairs, int E) {
    int e = blockIdx.x * blockDim.x + threadIdx.x;
    if (e >= E) return;
    int d = dst[e];
    float we = w[e];
    atomicAdd(&deg[d], we);
    int pos = atomicAdd(&cursor[d], 1);
    if (pos < CAP) {
        uint2 p;
        p.x = (unsigned)src[e];
        p.y = __float_as_uint(we);
        pairs[(size_t)d * CAP + pos] = p;
    }
}

__global__ void deg_fin(float* deg, int n) {
    int i = blockIdx.x * blockDim.x + threadIdx.x;
    if (i < n) deg[i] = rsqrtf(1.0f + deg[i]);   // self-loop weight folded in
}

// ---------------- GEMM common ------------------------------------------------
#define MMAF16(d, a0, a1, a2, a3, b0, b1)                                     \
    asm volatile("mma.sync.aligned.m16n8k16.row.col.f32.f16.f16.f32 "         \
                 "{%0,%1,%2,%3}, {%4,%5,%6,%7}, {%8,%9}, {%0,%1,%2,%3};"      \
                 : "+f"(d[0]), "+f"(d[1]), "+f"(d[2]), "+f"(d[3])             \
                 : "r"(a0), "r"(a1), "r"(a2), "r"(a3), "r"(b0), "r"(b1))

__device__ __forceinline__ uint4 ldsm4(unsigned addr) {
    uint4 r;
    asm volatile("ldmatrix.sync.aligned.m8n8.x4.shared.b16 {%0,%1,%2,%3}, [%4];"
                 : "=r"(r.x), "=r"(r.y), "=r"(r.z), "=r"(r.w) : "r"(addr));
    return r;
}

#define PXW_OFF (64 * 68)
#define PLAIN_SMEM_WORDS (64 * 68 + 128 * 68)   // 52224 B

template <typename TIN, int OCC>
__global__ void __launch_bounds__(256, OCC)
gemm_tc(const TIN* __restrict__ X, const float* __restrict__ W,
        __half* __restrict__ O, int n, int ntiles) {
    extern __shared__ unsigned smu[];
    unsigned* xhf = smu;                       // [64][68]
    unsigned* whf = smu + PXW_OFF;             // [128][68]

    const int t = threadIdx.x;

    for (int i = t; i < 64 * 128; i += 256) {
        int k2 = i >> 7, nn = i & 127;
        float a = W[(size_t)(2 * k2) * 128 + nn];
        float b = W[(size_t)(2 * k2 + 1) * 128 + nn];
        __half2 h2 = __floats2half2_rn(a, b);
        whf[nn * 68 + k2] = *(unsigned*)&h2;
    }

    const int lane = t & 31, w = t >> 5;
    const int mb = (w & 3) * 16, nb = (w >> 2) * 64;
    const int gid = lane >> 2, tig = lane & 3;

    const unsigned sbase = (unsigned)__cvta_generic_to_shared(smu);
    const int mat = lane >> 3, r8 = lane & 7;
    unsigned aAddr = sbase + (unsigned)(((mb + (mat & 1) * 8 + r8) * 68
                                         + (mat >> 1) * 4) * 4);
    unsigned bAddr[4];
    #pragma unroll
    for (int p = 0; p < 4; p++)
        bAddr[p] = sbase + (unsigned)((PXW_OFF
                       + (nb + p * 16 + (mat >> 1) * 8 + r8) * 68
                       + (mat & 1) * 4) * 4);

    float4 pf32[8];
    uint4  pf16[4];
    const bool F32 = (sizeof(TIN) == 4);

    int tile = blockIdx.x;
    if (tile < ntiles) {
        if (F32) {
            const float4* Xv = (const float4*)((const float*)X
                                               + (size_t)tile * 64 * 128);
            #pragma unroll
            for (int i = 0; i < 8; i++) {
                int idx = t + i * 256, r = idx >> 5;
                pf32[i] = make_float4(0.f, 0.f, 0.f, 0.f);
                if (tile * 64 + r < n) pf32[i] = Xv[idx];
            }
        } else {
            const uint4* Xv = (const uint4*)((const __half*)X
                                             + (size_t)tile * 64 * 128);
            #pragma unroll
            for (int i = 0; i < 4; i++) {
                int idx = t + i * 256, r = idx >> 4;
                pf16[i] = make_uint4(0u, 0u, 0u, 0u);
                if (tile * 64 + r < n) pf16[i] = Xv[idx];
            }
        }
    }

    while (tile < ntiles) {
        __syncthreads();
        if (F32) {
            #pragma unroll
            for (int i = 0; i < 8; i++) {
                int idx = t + i * 256;
                int r = idx >> 5, c4 = idx & 31;
                float4 v = pf32[i];
                __half2 h0 = __floats2half2_rn(v.x, v.y);
                __half2 h1 = __floats2half2_rn(v.z, v.w);
                xhf[r * 68 + 2 * c4]     = *(unsigned*)&h0;
                xhf[r * 68 + 2 * c4 + 1] = *(unsigned*)&h1;
            }
        } else {
            #pragma unroll
            for (int i = 0; i < 4; i++) {
                int idx = t + i * 256;
                int r = idx >> 4, c16 = idx & 15;
                xhf[r * 68 + c16 * 4]     = pf16[i].x;
                xhf[r * 68 + c16 * 4 + 1] = pf16[i].y;
                xhf[r * 68 + c16 * 4 + 2] = pf16[i].z;
                xhf[r * 68 + c16 * 4 + 3] = pf16[i].w;
            }
        }
        __syncthreads();

        const int next = tile + gridDim.x;
        if (next < ntiles) {
            if (F32) {
                const float4* Xv = (const float4*)((const float*)X
                                                   + (size_t)next * 64 * 128);
                #pragma unroll
                for (int i = 0; i < 8; i++) {
                    int idx = t + i * 256, r = idx >> 5;
                    pf32[i] = make_float4(0.f, 0.f, 0.f, 0.f);
                    if (next * 64 + r < n) pf32[i] = Xv[idx];
                }
            } else {
                const uint4* Xv = (const uint4*)((const __half*)X
                                                 + (size_t)next * 64 * 128);
                #pragma unroll
                for (int i = 0; i < 4; i++) {
                    int idx = t + i * 256, r = idx >> 4;
                    pf16[i] = make_uint4(0u, 0u, 0u, 0u);
                    if (next * 64 + r < n) pf16[i] = Xv[idx];
                }
            }
        }

        float acc[8][4];
        #pragma unroll
        for (int i = 0; i < 8; i++)
            #pragma unroll
            for (int j = 0; j < 4; j++) acc[i][j] = 0.f;

        #pragma unroll
        for (int kk = 0; kk < 8; kk++) {
            const unsigned off = kk * 32;
            uint4 a = ldsm4(aAddr + off);
            #pragma unroll
            for (int p = 0; p < 4; p++) {
                uint4 b = ldsm4(bAddr[p] + off);
                MMAF16(acc[2 * p],     a.x, a.y, a.z, a.w, b.x, b.y);
                MMAF16(acc[2 * p + 1], a.x, a.y, a.z, a.w, b.z, b.w);
            }
        }

        const int r0 = tile * 64 + mb + gid;
        #pragma unroll
        for (int nt = 0; nt < 8; nt++) {
            int c = nb + nt * 8 + 2 * tig;
            if (r0 < n)
                *(__half2*)&O[(size_t)r0 * 128 + c] =
                    __floats2half2_rn(acc[nt][0], acc[nt][1]);
            if (r0 + 8 < n)
                *(__half2*)&O[(size_t)(r0 + 8) * 128 + c] =
                    __floats2half2_rn(acc[nt][2], acc[nt][3]);
        }
        tile = next;
    }
}

// ---------------- fused aggregate + self-loop + bias + relu ----------------
__device__ __forceinline__ float4 h4_load(const __half* h, int node, int lane) {
    uint2 raw = ((const uint2*)(h + (size_t)node * C))[lane];
    float2 p0 = __half22float2(*(__half2*)&raw.x);
    float2 p1 = __half22float2(*(__half2*)&raw.y);
    return make_float4(p0.x, p0.y, p1.x, p1.y);
}

template <bool OUT16>
__global__ void aggregate(const __half* __restrict__ h,
                          const int* __restrict__ cursor,
                          const uint2* __restrict__ pairs,
                          const float* __restrict__ dinv,
                          const float* __restrict__ bias,
                          void* __restrict__ outv, int n) {
    int node = blockIdx.x * (blockDim.x >> 5) + (threadIdx.x >> 5);
    int lane = threadIdx.x & 31;
    if (node >= n) return;

    float di = dinv[node];
    float4 acc = h4_load(h, node, lane);
    acc.x *= di; acc.y *= di; acc.z *= di; acc.w *= di;

    const size_t base = (size_t)node * CAP;
    int cnt = cursor[node];
    cnt = cnt < CAP ? cnt : CAP;

    int j = 0;
    for (; j + 7 < cnt; j += 8) {
        uint2 p[8];
        #pragma unroll
        for (int k = 0; k < 8; k++) p[k] = pairs[base + j + k];
        #pragma unroll
        for (int k = 0; k < 8; k++) {
            int s = (int)p[k].x;
            float v = __uint_as_float(p[k].y) * dinv[s];
            float4 hh = h4_load(h, s, lane);
            acc.x += v * hh.x; acc.y += v * hh.y;
            acc.z += v * hh.z; acc.w += v * hh.w;
        }
    }
    for (; j + 3 < cnt; j += 4) {
        uint2 p[4];
        #pragma unroll
        for (int k = 0; k < 4; k++) p[k] = pairs[base + j + k];
        #pragma unroll
        for (int k = 0; k < 4; k++) {
            int s = (int)p[k].x;
            float v = __uint_as_float(p[k].y) * dinv[s];
            float4 hh = h4_load(h, s, lane);
            acc.x += v * hh.x; acc.y += v * hh.y;
            acc.z += v * hh.z; acc.w += v * hh.w;
        }
    }
    for (; j < cnt; j++) {
        uint2 p = pairs[base + j];
        int s = (int)p.x;
        float v = __uint_as_float(p.y) * dinv[s];
        float4 hh = h4_load(h, s, lane);
        acc.x += v * hh.x; acc.y += v * hh.y;
        acc.z += v * hh.z; acc.w += v * hh.w;
    }

    float4 bv = *(const float4*)&bias[lane * 4];
    acc.x = fmaxf(acc.x * di + bv.x, 0.f);
    acc.y = fmaxf(acc.y * di + bv.y, 0.f);
    acc.z = fmaxf(acc.z * di + bv.z, 0.f);
    acc.w = fmaxf(acc.w * di + bv.w, 0.f);

    if (OUT16) {
        __half* o = (__half*)outv;
        uint2 pk;
        __half2 p0 = __floats2half2_rn(acc.x, acc.y);
        __half2 p1 = __floats2half2_rn(acc.z, acc.w);
        pk.x = *(unsigned*)&p0; pk.y = *(unsigned*)&p1;
        ((uint2*)(o + (size_t)node * C))[lane] = pk;
    } else {
        float* o = (float*)outv;
        ((float4*)(o + (size_t)node * C))[lane] = acc;
    }
}

// ---------------------------------------------------------------------------
extern "C" void kernel_launch(void* const* d_in, const int* in_sizes, int n_in,
                              void* d_out, int out_size) {
    const float* x  = (const float*)d_in[0];
    const int*   ei = (const int*)d_in[1];     // [2, E] int32
    const float* ew = (const float*)d_in[2];
    const float* W1 = (const float*)d_in[3];
    const float* b1 = (const float*)d_in[4];
    const float* W2 = (const float*)d_in[5];
    const float* b2 = (const float*)d_in[6];
    float* out = (float*)d_out;

    const int N = in_sizes[0] / C;
    const int E = in_sizes[2];
    const int* src = ei;
    const int* dst = ei + E;

    float*  dinv;   cudaGetSymbolAddress((void**)&dinv, g_dinv);
    int*    cursor; cudaGetSymbolAddress((void**)&cursor, g_cursor);
    uint2*  pairs;  cudaGetSymbolAddress((void**)&pairs, g_pairs);
    __half* h16;    cudaGetSymbolAddress((void**)&h16, g_h16);
    __half* a16;    cudaGetSymbolAddress((void**)&a16, g_a16);

    const int PLAIN_SMEM = PLAIN_SMEM_WORDS * (int)sizeof(unsigned);
    cudaFuncSetAttribute(gemm_tc<float, 2>,
                         cudaFuncAttributeMaxDynamicSharedMemorySize, PLAIN_SMEM);
    cudaFuncSetAttribute(gemm_tc<__half, 3>,
                         cudaFuncAttributeMaxDynamicSharedMemorySize, PLAIN_SMEM);

    static cudaStream_t s2 = nullptr;
    static cudaEvent_t evFork = nullptr, ev2 = nullptr;
    if (!s2) {
        cudaStreamCreateWithFlags(&s2, cudaStreamNonBlocking);
        cudaEventCreateWithFlags(&evFork, cudaEventDisableTiming);
        cudaEventCreateWithFlags(&ev2, cudaEventDisableTiming);
    }

    dim3 blk(256);
    int gN     = (N + 255) / 256;
    int gE     = (E + 255) / 256;
    int ntiles = (N + 63) / 64;
    int gF32   = 296 < ntiles ? 296 : ntiles;   // 2 CTA/SM persistent
    int gF16   = 444 < ntiles ? 444 : ntiles;   // 3 CTA/SM persistent
    int gAgg   = (N + 7) / 8;

    // ---- fork: layer-1 GEMM on s2 (independent of graph structure) ---------
    cudaEventRecord(evFork, 0);
    cudaStreamWaitEvent(s2, evFork, 0);
    gemm_tc<float, 2><<<gF32, blk, PLAIN_SMEM, s2>>>(x, W1, h16, N, ntiles);
    cudaEventRecord(ev2, s2);

    // ---- CSR build on main stream (hidden under gemm1) ----------------------
    init_zero<<<gN, blk>>>(dinv, cursor, N);
    edge_build<<<gE, blk>>>(src, dst, ew, dinv, cursor, pairs, E);
    deg_fin<<<gN, blk>>>(dinv, N);

    cudaStreamWaitEvent(0, ev2, 0);

    // ---- layer 1 aggregate (fp16 activation out) ----
    aggregate<true><<<gAgg, blk>>>(h16, cursor, pairs, dinv, b1, a16, N);

    // ---- layer 2 ----
    gemm_tc<__half, 3><<<gF16, blk, PLAIN_SMEM>>>(a16, W2, h16, N, ntiles);
    aggregate<false><<<gAgg, blk>>>(h16, cursor, pairs, dinv, b2, out, N);
}

// round 17
// speedup vs baseline: 1.2493x; 1.0181x over previous
#include <cuda_runtime.h>
#include <cuda_bf16.h>
#include <cuda_fp16.h>

// ---------------------------------------------------------------------------
// 2-layer GCN. Bucketed CSR (CAP=96 >> Poisson(12) max degree), (src,w) packed
// uint2. Fork: gemm1 on s2, bucket_fill on s3, degree chain on main.
// Serial tail: agg1 -> gemm2 -> agg2.
// Locked-in post-mortems: aggregate stays standalone (R15); no agg/gemm
// stream overlap (R12/13); split edge passes beat merged (R16).
// This round: gemm1 (fp32 input) raised to 3 CTA/SM via launch_bounds.
// ---------------------------------------------------------------------------

#define C 128
#define NMAX 50048
#define CAP 96

__device__ float  g_dinv[NMAX];
__device__ int    g_cursor[NMAX];
__device__ uint2  g_pairs[(size_t)NMAX * CAP];   // (src, f32 bits of weight)
__device__ __half g_h16[(size_t)NMAX * C];   // GEMM result (fp16)
__device__ __half g_a16[(size_t)NMAX * C];   // layer-1 activation (fp16)

// ---------------- init ------------------------------------------------------
__global__ void init_zero(float* deg, int* cursor, int n) {
    int i = blockIdx.x * blockDim.x + threadIdx.x;
    if (i < n) { deg[i] = 0.0f; cursor[i] = 0; }
}

__global__ void deg_scatter(const int* __restrict__ dst,
                            const float* __restrict__ w,
                            float* deg, int E) {
    int e = blockIdx.x * blockDim.x + threadIdx.x;
    if (e < E) atomicAdd(&deg[dst[e]], w[e]);
}

__global__ void deg_fin(float* deg, int n) {
    int i = blockIdx.x * blockDim.x + threadIdx.x;
    if (i < n) deg[i] = rsqrtf(1.0f + deg[i]);   // self-loop weight folded in
}

// ---------------- bucket fill (independent of degree pass) ------------------
__global__ void bucket_fill(const int* __restrict__ src,
                            const int* __restrict__ dst,
                            const float* __restrict__ w,
                            int* cursor, uint2* __restrict__ pairs, int E) {
    int e = blockIdx.x * blockDim.x + threadIdx.x;
    if (e >= E) return;
    int d = dst[e];
    int pos = atomicAdd(&cursor[d], 1);
    if (pos < CAP) {
        uint2 p;
        p.x = (unsigned)src[e];
        p.y = __float_as_uint(w[e]);
        pairs[(size_t)d * CAP + pos] = p;
    }
}

// ---------------- GEMM common ------------------------------------------------
#define MMAF16(d, a0, a1, a2, a3, b0, b1)                                     \
    asm volatile("mma.sync.aligned.m16n8k16.row.col.f32.f16.f16.f32 "         \
                 "{%0,%1,%2,%3}, {%4,%5,%6,%7}, {%8,%9}, {%0,%1,%2,%3};"      \
                 : "+f"(d[0]), "+f"(d[1]), "+f"(d[2]), "+f"(d[3])             \
                 : "r"(a0), "r"(a1), "r"(a2), "r"(a3), "r"(b0), "r"(b1))

__device__ __forceinline__ uint4 ldsm4(unsigned addr) {
    uint4 r;
    asm volatile("ldmatrix.sync.aligned.m8n8.x4.shared.b16 {%0,%1,%2,%3}, [%4];"
                 : "=r"(r.x), "=r"(r.y), "=r"(r.z), "=r"(r.w) : "r"(addr));
    return r;
}

#define PXW_OFF (64 * 68)
#define PLAIN_SMEM_WORDS (64 * 68 + 128 * 68)   // 52224 B

template <typename TIN, int OCC>
__global__ void __launch_bounds__(256, OCC)
gemm_tc(const TIN* __restrict__ X, const float* __restrict__ W,
        __half* __restrict__ O, int n, int ntiles) {
    extern __shared__ unsigned smu[];
    unsigned* xhf = smu;                       // [64][68]
    unsigned* whf = smu + PXW_OFF;             // [128][68]

    const int t = threadIdx.x;

    for (int i = t; i < 64 * 128; i += 256) {
        int k2 = i >> 7, nn = i & 127;
        float a = W[(size_t)(2 * k2) * 128 + nn];
        float b = W[(size_t)(2 * k2 + 1) * 128 + nn];
        __half2 h2 = __floats2half2_rn(a, b);
        whf[nn * 68 + k2] = *(unsigned*)&h2;
    }

    const int lane = t & 31, w = t >> 5;
    const int mb = (w & 3) * 16, nb = (w >> 2) * 64;
    const int gid = lane >> 2, tig = lane & 3;

    const unsigned sbase = (unsigned)__cvta_generic_to_shared(smu);
    const int mat = lane >> 3, r8 = lane & 7;
    unsigned aAddr = sbase + (unsigned)(((mb + (mat & 1) * 8 + r8) * 68
                                         + (mat >> 1) * 4) * 4);
    unsigned bAddr[4];
    #pragma unroll
    for (int p = 0; p < 4; p++)
        bAddr[p] = sbase + (unsigned)((PXW_OFF
                       + (nb + p * 16 + (mat >> 1) * 8 + r8) * 68
                       + (mat & 1) * 4) * 4);

    float4 pf32[8];
    uint4  pf16[4];
    const bool F32 = (sizeof(TIN) == 4);

    int tile = blockIdx.x;
    if (tile < ntiles) {
        if (F32) {
            const float4* Xv = (const float4*)((const float*)X
                                               + (size_t)tile * 64 * 128);
            #pragma unroll
            for (int i = 0; i < 8; i++) {
                int idx = t + i * 256, r = idx >> 5;
                pf32[i] = make_float4(0.f, 0.f, 0.f, 0.f);
                if (tile * 64 + r < n) pf32[i] = Xv[idx];
            }
        } else {
            const uint4* Xv = (const uint4*)((const __half*)X
                                             + (size_t)tile * 64 * 128);
            #pragma unroll
            for (int i = 0; i < 4; i++) {
                int idx = t + i * 256, r = idx >> 4;
                pf16[i] = make_uint4(0u, 0u, 0u, 0u);
                if (tile * 64 + r < n) pf16[i] = Xv[idx];
            }
        }
    }

    while (tile < ntiles) {
        __syncthreads();
        if (F32) {
            #pragma unroll
            for (int i = 0; i < 8; i++) {
                int idx = t + i * 256;
                int r = idx >> 5, c4 = idx & 31;
                float4 v = pf32[i];
                __half2 h0 = __floats2half2_rn(v.x, v.y);
                __half2 h1 = __floats2half2_rn(v.z, v.w);
                xhf[r * 68 + 2 * c4]     = *(unsigned*)&h0;
                xhf[r * 68 + 2 * c4 + 1] = *(unsigned*)&h1;
            }
        } else {
            #pragma unroll
            for (int i = 0; i < 4; i++) {
                int idx = t + i * 256;
                int r = idx >> 4, c16 = idx & 15;
                xhf[r * 68 + c16 * 4]     = pf16[i].x;
                xhf[r * 68 + c16 * 4 + 1] = pf16[i].y;
                xhf[r * 68 + c16 * 4 + 2] = pf16[i].z;
                xhf[r * 68 + c16 * 4 + 3] = pf16[i].w;
            }
        }
        __syncthreads();

        const int next = tile + gridDim.x;
        if (next < ntiles) {
            if (F32) {
                const float4* Xv = (const float4*)((const float*)X
                                                   + (size_t)next * 64 * 128);
                #pragma unroll
                for (int i = 0; i < 8; i++) {
                    int idx = t + i * 256, r = idx >> 5;
                    pf32[i] = make_float4(0.f, 0.f, 0.f, 0.f);
                    if (next * 64 + r < n) pf32[i] = Xv[idx];
                }
            } else {
                const uint4* Xv = (const uint4*)((const __half*)X
                                                 + (size_t)next * 64 * 128);
                #pragma unroll
                for (int i = 0; i < 4; i++) {
                    int idx = t + i * 256, r = idx >> 4;
                    pf16[i] = make_uint4(0u, 0u, 0u, 0u);
                    if (next * 64 + r < n) pf16[i] = Xv[idx];
                }
            }
        }

        float acc[8][4];
        #pragma unroll
        for (int i = 0; i < 8; i++)
            #pragma unroll
            for (int j = 0; j < 4; j++) acc[i][j] = 0.f;

        #pragma unroll
        for (int kk = 0; kk < 8; kk++) {
            const unsigned off = kk * 32;
            uint4 a = ldsm4(aAddr + off);
            #pragma unroll
            for (int p = 0; p < 4; p++) {
                uint4 b = ldsm4(bAddr[p] + off);
                MMAF16(acc[2 * p],     a.x, a.y, a.z, a.w, b.x, b.y);
                MMAF16(acc[2 * p + 1], a.x, a.y, a.z, a.w, b.z, b.w);
            }
        }

        const int r0 = tile * 64 + mb + gid;
        #pragma unroll
        for (int nt = 0; nt < 8; nt++) {
            int c = nb + nt * 8 + 2 * tig;
            if (r0 < n)
                *(__half2*)&O[(size_t)r0 * 128 + c] =
                    __floats2half2_rn(acc[nt][0], acc[nt][1]);
            if (r0 + 8 < n)
                *(__half2*)&O[(size_t)(r0 + 8) * 128 + c] =
                    __floats2half2_rn(acc[nt][2], acc[nt][3]);
        }
        tile = next;
    }
}

// ---------------- fused aggregate + self-loop + bias + relu ----------------
__device__ __forceinline__ float4 h4_load(const __half* h, int node, int lane) {
    uint2 raw = ((const uint2*)(h + (size_t)node * C))[lane];
    float2 p0 = __half22float2(*(__half2*)&raw.x);
    float2 p1 = __half22float2(*(__half2*)&raw.y);
    return make_float4(p0.x, p0.y, p1.x, p1.y);
}

template <bool OUT16>
__global__ void aggregate(const __half* __restrict__ h,
                          const int* __restrict__ cursor,
                          const uint2* __restrict__ pairs,
                          const float* __restrict__ dinv,
                          const float* __restrict__ bias,
                          void* __restrict__ outv, int n) {
    int node = blockIdx.x * (blockDim.x >> 5) + (threadIdx.x >> 5);
    int lane = threadIdx.x & 31;
    if (node >= n) return;

    float di = dinv[node];
    float4 acc = h4_load(h, node, lane);
    acc.x *= di; acc.y *= di; acc.z *= di; acc.w *= di;

    const size_t base = (size_t)node * CAP;
    int cnt = cursor[node];
    cnt = cnt < CAP ? cnt : CAP;

    int j = 0;
    for (; j + 7 < cnt; j += 8) {
        uint2 p[8];
        #pragma unroll
        for (int k = 0; k < 8; k++) p[k] = pairs[base + j + k];
        #pragma unroll
        for (int k = 0; k < 8; k++) {
            int s = (int)p[k].x;
            float v = __uint_as_float(p[k].y) * dinv[s];
            float4 hh = h4_load(h, s, lane);
            acc.x += v * hh.x; acc.y += v * hh.y;
            acc.z += v * hh.z; acc.w += v * hh.w;
        }
    }
    for (; j + 3 < cnt; j += 4) {
        uint2 p[4];
        #pragma unroll
        for (int k = 0; k < 4; k++) p[k] = pairs[base + j + k];
        #pragma unroll
        for (int k = 0; k < 4; k++) {
            int s = (int)p[k].x;
            float v = __uint_as_float(p[k].y) * dinv[s];
            float4 hh = h4_load(h, s, lane);
            acc.x += v * hh.x; acc.y += v * hh.y;
            acc.z += v * hh.z; acc.w += v * hh.w;
        }
    }
    for (; j < cnt; j++) {
        uint2 p = pairs[base + j];
        int s = (int)p.x;
        float v = __uint_as_float(p.y) * dinv[s];
        float4 hh = h4_load(h, s, lane);
        acc.x += v * hh.x; acc.y += v * hh.y;
        acc.z += v * hh.z; acc.w += v * hh.w;
    }

    float4 bv = *(const float4*)&bias[lane * 4];
    acc.x = fmaxf(acc.x * di + bv.x, 0.f);
    acc.y = fmaxf(acc.y * di + bv.y, 0.f);
    acc.z = fmaxf(acc.z * di + bv.z, 0.f);
    acc.w = fmaxf(acc.w * di + bv.w, 0.f);

    if (OUT16) {
        __half* o = (__half*)outv;
        uint2 pk;
        __half2 p0 = __floats2half2_rn(acc.x, acc.y);
        __half2 p1 = __floats2half2_rn(acc.z, acc.w);
        pk.x = *(unsigned*)&p0; pk.y = *(unsigned*)&p1;
        ((uint2*)(o + (size_t)node * C))[lane] = pk;
    } else {
        float* o = (float*)outv;
        ((float4*)(o + (size_t)node * C))[lane] = acc;
    }
}

// ---------------------------------------------------------------------------
extern "C" void kernel_launch(void* const* d_in, const int* in_sizes, int n_in,
                              void* d_out, int out_size) {
    const float* x  = (const float*)d_in[0];
    const int*   ei = (const int*)d_in[1];     // [2, E] int32
    const float* ew = (const float*)d_in[2];
    const float* W1 = (const float*)d_in[3];
    const float* b1 = (const float*)d_in[4];
    const float* W2 = (const float*)d_in[5];
    const float* b2 = (const float*)d_in[6];
    float* out = (float*)d_out;

    const int N = in_sizes[0] / C;
    const int E = in_sizes[2];
    const int* src = ei;
    const int* dst = ei + E;

    float*  dinv;   cudaGetSymbolAddress((void**)&dinv, g_dinv);
    int*    cursor; cudaGetSymbolAddress((void**)&cursor, g_cursor);
    uint2*  pairs;  cudaGetSymbolAddress((void**)&pairs, g_pairs);
    __half* h16;    cudaGetSymbolAddress((void**)&h16, g_h16);
    __half* a16;    cudaGetSymbolAddress((void**)&a16, g_a16);

    const int PLAIN_SMEM = PLAIN_SMEM_WORDS * (int)sizeof(unsigned);
    cudaFuncSetAttribute(gemm_tc<float, 3>,
                         cudaFuncAttributeMaxDynamicSharedMemorySize, PLAIN_SMEM);
    cudaFuncSetAttribute(gemm_tc<__half, 3>,
                         cudaFuncAttributeMaxDynamicSharedMemorySize, PLAIN_SMEM);

    static cudaStream_t s2 = nullptr, s3 = nullptr;
    static cudaEvent_t evFork = nullptr, evM = nullptr, ev2 = nullptr,
                       ev3 = nullptr;
    if (!s2) {
        cudaStreamCreateWithFlags(&s2, cudaStreamNonBlocking);
        cudaStreamCreateWithFlags(&s3, cudaStreamNonBlocking);
        cudaEventCreateWithFlags(&evFork, cudaEventDisableTiming);
        cudaEventCreateWithFlags(&evM, cudaEventDisableTiming);
        cudaEventCreateWithFlags(&ev2, cudaEventDisableTiming);
        cudaEventCreateWithFlags(&ev3, cudaEventDisableTiming);
    }

    dim3 blk(256);
    int gN     = (N + 255) / 256;
    int gE     = (E + 255) / 256;
    int ntiles = (N + 63) / 64;
    int gF32   = 444 < ntiles ? 444 : ntiles;   // 3 CTA/SM persistent
    int gF16   = 444 < ntiles ? 444 : ntiles;   // 3 CTA/SM persistent
    int gAgg   = (N + 7) / 8;

    // ---- fork A: layer-1 GEMM on s2 (independent of graph structure) -------
    cudaEventRecord(evFork, 0);
    cudaStreamWaitEvent(s2, evFork, 0);
    gemm_tc<float, 3><<<gF32, blk, PLAIN_SMEM, s2>>>(x, W1, h16, N, ntiles);
    cudaEventRecord(ev2, s2);

    // ---- main: init, then fork B: bucket fill on s3 concurrent with degree -
    init_zero<<<gN, blk>>>(dinv, cursor, N);
    cudaEventRecord(evM, 0);
    cudaStreamWaitEvent(s3, evM, 0);
    bucket_fill<<<gE, blk, 0, s3>>>(src, dst, ew, cursor, pairs, E);
    cudaEventRecord(ev3, s3);

    deg_scatter<<<gE, blk>>>(dst, ew, dinv, E);
    deg_fin<<<gN, blk>>>(dinv, N);

    cudaStreamWaitEvent(0, ev3, 0);
    cudaStreamWaitEvent(0, ev2, 0);

    // ---- layer 1 aggregate (fp16 activation out) ----
    aggregate<true><<<gAgg, blk>>>(h16, cursor, pairs, dinv, b1, a16, N);

    // ---- layer 2 ----
    gemm_tc<__half, 3><<<gF16, blk, PLAIN_SMEM>>>(a16, W2, h16, N, ntiles);
    aggregate<false><<<gAgg, blk>>>(h16, cursor, pairs, dinv, b2, out, N);
}